// round 17
// baseline (speedup 1.0000x reference)
#include <cuda_runtime.h>
#include <cstdint>

#define IMG_N  2048
#define OW     2044
#define OH     2044
#define TW     128
#define TH     8
#define IR     12          // TH + 4 input rows
#define IC     132         // TW + 4 input cols
#define ICP    136         // padded col stride (bf16) — 272B rows, 16B aligned
#define NTH    128         // 16 col-groups x 8 rows

// smem layout (bytes)
#define SX_OFF     0
#define SX_BYTES   (IR * IC * 4)               // 6336: raw int tile
#define PL_OFF     SX_BYTES                    // bf16 planes [IR][6][ICP]
#define PL_BYTES   (IR * 6 * ICP * 2)          // 19584
#define SMEM_BYTES (PL_OFF + PL_BYTES)         // 25920

typedef unsigned long long ull;
typedef unsigned int u32;

__constant__ float c_w[75];                     // weight[d][i][j] = d*25+i*5+j

__device__ __forceinline__ void fma2(ull& acc, ull a, ull b) {
    asm("fma.rn.f32x2 %0, %1, %2, %0;" : "+l"(acc) : "l"(a), "l"(b));
}
__device__ __forceinline__ ull dup2(float w) {
    ull r; asm("mov.b64 %0, {%1, %1};" : "=l"(r) : "f"(w)); return r;
}
__device__ __forceinline__ ull mkpair_lohi(u32 u) {
    ull r;
    asm("{.reg .b32 a, b;\n\t"
        "shl.b32 a, %1, 16;\n\t"
        "and.b32 b, %1, 0xFFFF0000;\n\t"
        "mov.b64 %0, {a, b};}" : "=l"(r) : "r"(u));
    return r;
}
__device__ __forceinline__ ull mkpair_cross(u32 u, u32 v) {
    ull r;
    asm("{.reg .b32 a, b;\n\t"
        "and.b32 a, %1, 0xFFFF0000;\n\t"
        "shl.b32 b, %2, 16;\n\t"
        "mov.b64 %0, {a, b};}" : "=l"(r) : "r"(u), "r"(v));
    return r;
}

// Expand np bit-planes [z0, z0+np) of the int tile into bf16 planes (exact).
__device__ __forceinline__ void expand_planes(const int* __restrict__ sx,
                                              uint16_t* __restrict__ pl,
                                              int tid, int z0, int np)
{
    for (int idx = tid; idx < IR * (IC / 2); idx += NTH) {
        int rr = idx / (IC / 2);
        int c2 = (idx - rr * (IC / 2)) * 2;
        const int* src = sx + rr * IC + c2;
        u32 v0 = (u32)src[0] >> z0;
        u32 v1 = (u32)src[1] >> z0;
        u32* dst = reinterpret_cast<u32*>(pl + (rr * 6) * ICP + c2);
        #pragma unroll 6
        for (int p = 0; p < np; p++) {
            u32 val = ((v0 >> p) & 1u) * 0x3F80u
                    | ((v1 >> p) & 1u) * 0x3F800000u;
            dst[p * (ICP / 2)] = val;
        }
    }
}

// One z-pass: NZ outputs, staged planes p in [0, NZ+2), 8 cols/thread.
// acc[z][p] = output pair (col0+2p, col0+2p+1).
template<int NZ>
__device__ __forceinline__ void run_pass(const uint16_t* __restrict__ sp,
                                         int r, int col0, ull acc[][4])
{
    #pragma unroll
    for (int z = 0; z < NZ; z++)
        #pragma unroll
        for (int p = 0; p < 4; p++) acc[z][p] = 0ull;

    #pragma unroll 1
    for (int i = 0; i < 5; i++) {
        // 15 weight pairs for this i from constant bank (uniform path, no RF cost)
        ull wv[15];
        #pragma unroll
        for (int d = 0; d < 3; d++)
            #pragma unroll
            for (int j = 0; j < 5; j++)
                wv[d * 5 + j] = dup2(c_w[d * 25 + i * 5 + j]);

        const uint16_t* rowi = sp + ((r + i) * 6) * ICP + col0;

        #pragma unroll
        for (int kk = 0; kk < NZ + 2; kk++) {
            const uint4* rk = reinterpret_cast<const uint4*>(rowi + kk * ICP);
            uint4 qa = rk[0];          // bf16 cols 0..7  (u0..u3)
            uint2 qb = *reinterpret_cast<const uint2*>(
                reinterpret_cast<const u32*>(rk) + 4);   // cols 8..11 (u4,u5)
            u32 u0 = qa.x, u1 = qa.y, u2 = qa.z, u3 = qa.w, u4 = qb.x, u5 = qb.y;

            // S[m] = fp32 pair (v_m, v_{m+1}), v = bf16 cols 0..11
            ull S[11];
            S[0]  = mkpair_lohi (u0);
            S[2]  = mkpair_lohi (u1);
            S[4]  = mkpair_lohi (u2);
            S[6]  = mkpair_lohi (u3);
            S[8]  = mkpair_lohi (u4);
            S[10] = mkpair_lohi (u5);
            S[1]  = mkpair_cross(u0, u1);
            S[3]  = mkpair_cross(u1, u2);
            S[5]  = mkpair_cross(u2, u3);
            S[7]  = mkpair_cross(u3, u4);
            S[9]  = mkpair_cross(u4, u5);

            #pragma unroll
            for (int d = 0; d < 3; d++) {
                const int zz = kk - d;                 // compile-time per (kk,d)
                if (zz >= 0 && zz < NZ) {
                    #pragma unroll
                    for (int j = 0; j < 5; j++) {
                        const ull w = wv[d * 5 + j];
                        fma2(acc[zz][0], w, S[j]);
                        fma2(acc[zz][1], w, S[j + 2]);
                        fma2(acc[zz][2], w, S[j + 4]);
                        fma2(acc[zz][3], w, S[j + 6]);
                    }
                }
            }
        }
    }
}

template<int NZ>
__device__ __forceinline__ void store_pass(float* __restrict__ out, int h, int w,
                                           int z0, float bv, ull acc[][4])
{
    if (h >= OH || w >= OW) return;
    #pragma unroll
    for (int zz = 0; zz < NZ; zz++) {
        size_t off = ((size_t)(z0 + zz) * OH + h) * OW + w;
        float2 a0 = *reinterpret_cast<const float2*>(&acc[zz][0]);
        float2 a1 = *reinterpret_cast<const float2*>(&acc[zz][1]);
        float2 a2 = *reinterpret_cast<const float2*>(&acc[zz][2]);
        float2 a3 = *reinterpret_cast<const float2*>(&acc[zz][3]);
        if (w + 8 <= OW) {
            *reinterpret_cast<float4*>(out + off) =
                make_float4(a0.x + bv, a0.y + bv, a1.x + bv, a1.y + bv);
            *reinterpret_cast<float4*>(out + off + 4) =
                make_float4(a2.x + bv, a2.y + bv, a3.x + bv, a3.y + bv);
        } else {
            float vals[8] = { a0.x + bv, a0.y + bv, a1.x + bv, a1.y + bv,
                              a2.x + bv, a2.y + bv, a3.x + bv, a3.y + bv };
            #pragma unroll
            for (int c = 0; c < 8; c++)
                if (w + c < OW) out[off + c] = vals[c];
        }
    }
}

__global__ void __launch_bounds__(NTH, 8)
conv2dto3d_kernel(const int* __restrict__ x,
                  const float* __restrict__ bias,
                  float* __restrict__ out)
{
    extern __shared__ unsigned char smem[];
    int*       sx = reinterpret_cast<int*>(smem + SX_OFF);
    uint16_t*  pl = reinterpret_cast<uint16_t*>(smem + PL_OFF);

    const int tid   = threadIdx.x;
    const int wbase = blockIdx.x * TW;
    const int hbase = blockIdx.y * TH;

    // ---- load int tile (clamped) ----
    for (int idx = tid; idx < IR * IC; idx += NTH) {
        int rr = idx / IC, cc = idx - rr * IC;
        int ri = hbase + rr; if (ri > IMG_N - 1) ri = IMG_N - 1;
        int ci = wbase + cc; if (ci > IMG_N - 1) ci = IMG_N - 1;
        sx[idx] = x[ri * IMG_N + ci];
    }
    __syncthreads();

    const int g = tid & 15;          // 16 column groups of 8
    const int r = tid >> 4;          // local row 0..7
    const int col0 = g * 8;
    const int h = hbase + r;
    const int w = wbase + col0;
    const float bv = bias[0];

    {
        ull acc[4][4];
        // pass 0: z in [0..3], planes 0..5
        expand_planes(sx, pl, tid, 0, 6);
        __syncthreads();
        run_pass<4>(pl, r, col0, acc);
        __syncthreads();
        store_pass<4>(out, h, w, 0, bv, acc);

        // pass 1: z in [4..7], planes 4..9
        expand_planes(sx, pl, tid, 4, 6);
        __syncthreads();
        run_pass<4>(pl, r, col0, acc);
        __syncthreads();
        store_pass<4>(out, h, w, 4, bv, acc);

        // pass 2: z in [8..11], planes 8..13
        expand_planes(sx, pl, tid, 8, 6);
        __syncthreads();
        run_pass<4>(pl, r, col0, acc);
        __syncthreads();
        store_pass<4>(out, h, w, 8, bv, acc);
    }
    {
        ull acc[2][4];
        // pass 3: z in [12..13], planes 12..15
        expand_planes(sx, pl, tid, 12, 4);
        __syncthreads();
        run_pass<2>(pl, r, col0, acc);
        store_pass<2>(out, h, w, 12, bv, acc);
    }
}

extern "C" void kernel_launch(void* const* d_in, const int* in_sizes, int n_in,
                              void* d_out, int out_size)
{
    const int*   x      = (const int*)d_in[0];
    const float* weight = (const float*)d_in[1];
    const float* bias   = (const float*)d_in[2];
    float*       out    = (float*)d_out;

    cudaMemcpyToSymbolAsync(c_w, weight, 75 * sizeof(float), 0,
                            cudaMemcpyDeviceToDevice, 0);

    cudaFuncSetAttribute(conv2dto3d_kernel,
                         cudaFuncAttributeMaxDynamicSharedMemorySize, SMEM_BYTES);

    dim3 grid((OW + TW - 1) / TW, (OH + TH - 1) / TH);   // 16 x 256
    conv2dto3d_kernel<<<grid, NTH, SMEM_BYTES>>>(x, bias, out);
}